// round 3
// baseline (speedup 1.0000x reference)
#include <cuda_runtime.h>

#define Hh 8
#define Dd 64
#define Ss 32
#define Bg 8
#define DIMM 256
#define INNER 512
#define MAXN 30720
#define CHUNK 128

// ---------------- scratch (static device globals; no allocation) ----------------
__device__ float g_fx[MAXN * INNER];        // fx = x@W_fx + b_fx       [N, 512]
__device__ float g_w[MAXN * 256];           // logits -> softmax w      [N, H*S=256]
__device__ float g_wcomb[256 * 256];        // W_x (.) W_slice folded   [256, 256]
__device__ float g_bcomb[256];
__device__ float g_st[Bg * Hh * Ss * Dd];   // slice_token accum        [B,H,S,D]
__device__ float g_sn[Bg * Hh * Ss];        // slice_norm accum         [B,H,S]
__device__ float g_ot[Bg * Hh * Ss * Dd];   // out_tok                  [B,H,S,D]
__device__ float g_m1[Bg * 256 * 256];      // out_tok (.) W_out folded [B, 256, 256]

// ---------------- prep: W_comb[k,h*32+s] = sum_d W_x[k,h*64+d]*W_slice[d,s] ----
__global__ void prep_wcomb(const float* __restrict__ W_x, const float* __restrict__ b_x,
                           const float* __restrict__ W_slice, const float* __restrict__ b_slice) {
    int k = blockIdx.x;          // 0..255
    int hs = threadIdx.x;        // 0..255
    int h = hs >> 5, s = hs & 31;
    float a = 0.f;
    #pragma unroll
    for (int d = 0; d < 64; d++)
        a += W_x[k * 512 + h * 64 + d] * W_slice[d * 32 + s];
    g_wcomb[k * 256 + hs] = a;
    if (k == 0) {
        float bb = b_slice[s];
        #pragma unroll
        for (int d = 0; d < 64; d++)
            bb += b_x[h * 64 + d] * W_slice[d * 32 + s];
        g_bcomb[hs] = bb;
    }
}

// ---------------- zero scatter accumulators ----------------
__global__ void zero_acc() {
    int i = blockIdx.x * blockDim.x + threadIdx.x;
    if (i < Bg * Hh * Ss * Dd) g_st[i] = 0.f;
    if (i < Bg * Hh * Ss) g_sn[i] = 0.f;
}

// ---------------- classic 128x128x16 register-tiled SGEMM + bias ----------------
// C[M,N] = A[M,K] @ B[K,N] + bias[N].  N,K multiples of 128/16; M guarded.
__global__ void sgemm_bias(int M, int N, int K,
                           const float* __restrict__ A, const float* __restrict__ B,
                           const float* __restrict__ bias, float* __restrict__ C) {
    __shared__ float As[16][128];
    __shared__ float Bs[16][128];
    int tid = threadIdx.x;
    int bx = blockIdx.x, by = blockIdx.y;
    int tcol = tid & 15, trow = tid >> 4;
    int aRow = tid >> 2, aCol = (tid & 3) << 2;
    int bRow = tid >> 5, bCol = (tid & 31) << 2;
    float acc[8][8];
    #pragma unroll
    for (int i = 0; i < 8; i++)
        #pragma unroll
        for (int j = 0; j < 8; j++) acc[i][j] = 0.f;

    for (int k0 = 0; k0 < K; k0 += 16) {
        #pragma unroll
        for (int i = 0; i < 2; i++) {
            int r = aRow + i * 64;
            int gr = by * 128 + r;
            float4 v = make_float4(0.f, 0.f, 0.f, 0.f);
            if (gr < M) v = *(const float4*)&A[(size_t)gr * K + k0 + aCol];
            As[aCol + 0][r] = v.x; As[aCol + 1][r] = v.y;
            As[aCol + 2][r] = v.z; As[aCol + 3][r] = v.w;
        }
        #pragma unroll
        for (int i = 0; i < 2; i++) {
            int r = bRow + i * 8;
            *(float4*)&Bs[r][bCol] = *(const float4*)&B[(size_t)(k0 + r) * N + bx * 128 + bCol];
        }
        __syncthreads();
        #pragma unroll
        for (int kk = 0; kk < 16; kk++) {
            float a[8], b[8];
            #pragma unroll
            for (int i = 0; i < 8; i++) a[i] = As[kk][trow * 8 + i];
            #pragma unroll
            for (int j = 0; j < 8; j++) b[j] = Bs[kk][tcol * 8 + j];
            #pragma unroll
            for (int i = 0; i < 8; i++)
                #pragma unroll
                for (int j = 0; j < 8; j++) acc[i][j] += a[i] * b[j];
        }
        __syncthreads();
    }
    #pragma unroll
    for (int i = 0; i < 8; i++) {
        int gr = by * 128 + trow * 8 + i;
        if (gr >= M) continue;
        #pragma unroll
        for (int j = 0; j < 8; j += 4) {
            int gc = bx * 128 + tcol * 8 + j;
            float4 o;
            o.x = acc[i][j + 0] + bias[gc + 0];
            o.y = acc[i][j + 1] + bias[gc + 1];
            o.z = acc[i][j + 2] + bias[gc + 2];
            o.w = acc[i][j + 3] + bias[gc + 3];
            *(float4*)&C[(size_t)gr * N + gc] = o;
        }
    }
}

// ---------------- tempered softmax over S=32 (in-place on g_w) ----------------
__global__ void softmax_kernel(float* __restrict__ wbuf, const float* __restrict__ temp, int total) {
    int gw = blockIdx.x * 8 + (threadIdx.x >> 5);   // gw = n*8 + h
    int lane = threadIdx.x & 31;
    if (gw >= total) return;
    float v = wbuf[(size_t)gw * 32 + lane] / temp[gw & 7];
    float m = v;
    #pragma unroll
    for (int o = 16; o; o >>= 1) m = fmaxf(m, __shfl_xor_sync(0xffffffffu, m, o));
    float e = expf(v - m);
    float s = e;
    #pragma unroll
    for (int o = 16; o; o >>= 1) s += __shfl_xor_sync(0xffffffffu, s, o);
    wbuf[(size_t)gw * 32 + lane] = e / s;
}

// ---------------- scatter: slice_token[b,h,s,:] += w[n,h,s]*fx[n,h,:] ----------
// batch is sorted; each block handles CHUNK contiguous nodes, accumulates in
// registers (thread owns (h,s), 64 d-accumulators), flushes with one atomic pass
// per distinct b in the chunk.
__global__ void scatter_kernel(const int* __restrict__ batch, int N) {
    __shared__ float s_w[256];
    __shared__ float s_fx[512];
    __shared__ int s_b[CHUNK];
    int tid = threadIdx.x;
    int start = blockIdx.x * CHUNK;
    int end = min(start + CHUNK, N);
    int cnt = end - start;
    for (int i = tid; i < cnt; i += 256) s_b[i] = batch[start + i];
    __syncthreads();
    int b0 = s_b[0], b1 = s_b[cnt - 1];
    int h = tid >> 5;

    for (int bb = b0; bb <= b1; bb++) {
        float acc[64];
        #pragma unroll
        for (int d = 0; d < 64; d++) acc[d] = 0.f;
        float accn = 0.f;
        for (int i = 0; i < cnt; i++) {
            if (s_b[i] != bb) continue;           // uniform across block
            int n = start + i;
            s_w[tid] = g_w[(size_t)n * 256 + tid];
            s_fx[tid] = g_fx[(size_t)n * 512 + tid];
            s_fx[tid + 256] = g_fx[(size_t)n * 512 + tid + 256];
            __syncthreads();
            float wv = s_w[tid];
            const float* fxh = &s_fx[h * 64];
            #pragma unroll
            for (int d = 0; d < 64; d++) acc[d] += wv * fxh[d];
            accn += wv;
            __syncthreads();
        }
        float* st = g_st + ((size_t)bb * 256 + tid) * 64;
        #pragma unroll
        for (int d = 0; d < 64; d++)
            if (acc[d] != 0.f || true) atomicAdd(&st[d], acc[d]);
        atomicAdd(&g_sn[bb * 256 + tid], accn);
    }
}

// ---------------- tiny attention over slice tokens, one block per (b,h) --------
__global__ void attention_kernel(const float* __restrict__ W_q, const float* __restrict__ W_k,
                                 const float* __restrict__ W_v) {
    int bh = blockIdx.x;   // b*8 + h
    __shared__ float st[32 * 64];
    __shared__ float q[32 * 64];
    __shared__ float kT[64 * 33];   // padded, transposed
    __shared__ float v[32 * 64];
    __shared__ float attn[32 * 32];
    int tid = threadIdx.x;
    const float* base = g_st + (size_t)bh * 2048;
    const float* nrm = g_sn + bh * 32;

    for (int i = tid; i < 2048; i += 256) {
        int s = i >> 6;
        st[i] = base[i] / (nrm[s] + 1e-5f);
    }
    __syncthreads();
    for (int i = tid; i < 2048; i += 256) {
        int s = i >> 6, e = i & 63;
        float aq = 0.f, ak = 0.f, av = 0.f;
        #pragma unroll
        for (int d = 0; d < 64; d++) {
            float sv = st[s * 64 + d];
            aq += sv * W_q[d * 64 + e];
            ak += sv * W_k[d * 64 + e];
            av += sv * W_v[d * 64 + e];
        }
        q[i] = aq; kT[e * 33 + s] = ak; v[i] = av;
    }
    __syncthreads();
    for (int i = tid; i < 1024; i += 256) {
        int s = i >> 5, t = i & 31;
        float a = 0.f;
        #pragma unroll
        for (int d = 0; d < 64; d++) a += q[s * 64 + d] * kT[d * 33 + t];
        attn[i] = a * 0.125f;   // D^-0.5
    }
    __syncthreads();
    int warp = tid >> 5, lane = tid & 31;
    for (int r = warp; r < 32; r += 8) {
        float val = attn[r * 32 + lane];
        float m = val;
        #pragma unroll
        for (int o = 16; o; o >>= 1) m = fmaxf(m, __shfl_xor_sync(0xffffffffu, m, o));
        float e = expf(val - m);
        float ssum = e;
        #pragma unroll
        for (int o = 16; o; o >>= 1) ssum += __shfl_xor_sync(0xffffffffu, ssum, o);
        attn[r * 32 + lane] = e / ssum;
    }
    __syncthreads();
    float* ob = g_ot + (size_t)bh * 2048;
    for (int i = tid; i < 2048; i += 256) {
        int s = i >> 6, d = i & 63;
        float a = 0.f;
        #pragma unroll
        for (int t = 0; t < 32; t++) a += attn[s * 32 + t] * v[t * 64 + d];
        ob[i] = a;
    }
}

// ---------------- fold out_tok with W_out: M1[b][h*32+s][j] ----------------
__global__ void build_m1(const float* __restrict__ W_out) {
    int bh = blockIdx.x;
    int h = bh & 7, b = bh >> 3;
    __shared__ float ot[2048];
    int tid = threadIdx.x;
    for (int i = tid; i < 2048; i += 256) ot[i] = g_ot[(size_t)bh * 2048 + i];
    __syncthreads();
    for (int i = tid; i < 8192; i += 256) {
        int s = i >> 8, j = i & 255;
        float a = 0.f;
        #pragma unroll
        for (int d = 0; d < 64; d++)
            a += ot[s * 64 + d] * W_out[(h * 64 + d) * 256 + j];
        g_m1[((size_t)b * 256 + h * 32 + s) * 256 + j] = a;
    }
}

// ---------------- final: out[n,:] = w[n,:] @ M1[batch[n]] + b_out ----------------
__global__ void final_gemm(int M, const int* __restrict__ batch,
                           const float* __restrict__ bias, float* __restrict__ C) {
    const int K = 256, N = 256;
    __shared__ float As[16][128];
    __shared__ float Bs[16][128];
    __shared__ int sb[128];
    int tid = threadIdx.x;
    int bx = blockIdx.x, by = blockIdx.y;
    int row0 = by * 128;
    int rows = min(128, M - row0);
    for (int i = tid; i < 128; i += 256) sb[i] = (i < rows) ? batch[row0 + i] : -1;
    __syncthreads();
    int b_first = sb[0], b_last = sb[rows - 1];
    int tcol = tid & 15, trow = tid >> 4;
    int aRow = tid >> 2, aCol = (tid & 3) << 2;
    int bRow = tid >> 5, bCol = (tid & 31) << 2;

    for (int bb = b_first; bb <= b_last; bb++) {
        const float* B = g_m1 + (size_t)bb * 256 * 256;
        float acc[8][8];
        #pragma unroll
        for (int i = 0; i < 8; i++)
            #pragma unroll
            for (int j = 0; j < 8; j++) acc[i][j] = 0.f;

        for (int k0 = 0; k0 < K; k0 += 16) {
            #pragma unroll
            for (int i = 0; i < 2; i++) {
                int r = aRow + i * 64;
                int gr = row0 + r;
                float4 v = make_float4(0.f, 0.f, 0.f, 0.f);
                if (gr < M) v = *(const float4*)&g_w[(size_t)gr * K + k0 + aCol];
                As[aCol + 0][r] = v.x; As[aCol + 1][r] = v.y;
                As[aCol + 2][r] = v.z; As[aCol + 3][r] = v.w;
            }
            #pragma unroll
            for (int i = 0; i < 2; i++) {
                int r = bRow + i * 8;
                *(float4*)&Bs[r][bCol] = *(const float4*)&B[(size_t)(k0 + r) * N + bx * 128 + bCol];
            }
            __syncthreads();
            #pragma unroll
            for (int kk = 0; kk < 16; kk++) {
                float a[8], b[8];
                #pragma unroll
                for (int i = 0; i < 8; i++) a[i] = As[kk][trow * 8 + i];
                #pragma unroll
                for (int j = 0; j < 8; j++) b[j] = Bs[kk][tcol * 8 + j];
                #pragma unroll
                for (int i = 0; i < 8; i++)
                    #pragma unroll
                    for (int j = 0; j < 8; j++) acc[i][j] += a[i] * b[j];
            }
            __syncthreads();
        }
        #pragma unroll
        for (int i = 0; i < 8; i++) {
            int r = trow * 8 + i;
            int gr = row0 + r;
            if (gr < M && sb[r] == bb) {
                #pragma unroll
                for (int j = 0; j < 8; j += 4) {
                    int gc = bx * 128 + tcol * 8 + j;
                    float4 o;
                    o.x = acc[i][j + 0] + bias[gc + 0];
                    o.y = acc[i][j + 1] + bias[gc + 1];
                    o.z = acc[i][j + 2] + bias[gc + 2];
                    o.w = acc[i][j + 3] + bias[gc + 3];
                    *(float4*)&C[(size_t)gr * 256 + gc] = o;
                }
            }
        }
    }
}

// ---------------- launch ----------------
extern "C" void kernel_launch(void* const* d_in, const int* in_sizes, int n_in,
                              void* d_out, int out_size) {
    const float* x       = (const float*)d_in[0];
    const int*   batch   = (const int*)d_in[1];
    const float* W_fx    = (const float*)d_in[2];
    const float* b_fx    = (const float*)d_in[3];
    const float* W_x     = (const float*)d_in[4];
    const float* b_x     = (const float*)d_in[5];
    const float* W_slice = (const float*)d_in[6];
    const float* b_slice = (const float*)d_in[7];
    const float* gtemp   = (const float*)d_in[8];
    const float* W_q     = (const float*)d_in[9];
    const float* W_k     = (const float*)d_in[10];
    const float* W_v     = (const float*)d_in[11];
    const float* W_out   = (const float*)d_in[12];
    const float* b_out   = (const float*)d_in[13];
    float* out = (float*)d_out;

    int n = in_sizes[1];           // batch element count = N
    int rowBlocks = (n + 127) / 128;

    float *p_fx, *p_w, *p_wcomb, *p_bcomb;
    cudaGetSymbolAddress((void**)&p_fx, g_fx);
    cudaGetSymbolAddress((void**)&p_w, g_w);
    cudaGetSymbolAddress((void**)&p_wcomb, g_wcomb);
    cudaGetSymbolAddress((void**)&p_bcomb, g_bcomb);

    // 1. fold W_x with W_slice
    prep_wcomb<<<256, 256>>>(W_x, b_x, W_slice, b_slice);
    // 2. zero scatter accumulators
    zero_acc<<<512, 256>>>();
    // 3. fx = x @ W_fx + b_fx            [N,512]
    sgemm_bias<<<dim3(4, rowBlocks), 256>>>(n, 512, 256, x, W_fx, b_fx, p_fx);
    // 4. logits = x @ W_comb + b_comb    [N,256]  (into g_w, softmaxed in place)
    sgemm_bias<<<dim3(2, rowBlocks), 256>>>(n, 256, 256, x, p_wcomb, p_bcomb, p_w);
    // 5. tempered softmax over S
    softmax_kernel<<<(n * 8 + 7) / 8, 256>>>(p_w, gtemp, n * 8);
    // 6. scatter-add pooling
    scatter_kernel<<<(n + CHUNK - 1) / CHUNK, 256>>>(batch, n);
    // 7. tiny attention over slice tokens
    attention_kernel<<<64, 256>>>(W_q, W_k, W_v);
    // 8. fold out_tok with W_out
    build_m1<<<64, 256>>>(W_out);
    // 9. out = w @ M1[batch] + b_out
    final_gemm<<<dim3(2, rowBlocks), 256>>>(n, batch, b_out, out);
}

// round 5
// speedup vs baseline: 1.1212x; 1.1212x over previous
#include <cuda_runtime.h>

#define Hh 8
#define Dd 64
#define Ss 32
#define Bg 8
#define MAXN 30720
#define CHUNK 128

// ---------------- scratch (static device globals; no allocation) ----------------
__device__ float g_cat[MAXN * 768];         // [N, 768]: cols 0..511 fx, 512..767 w
__device__ float g_bigW[256 * 768];         // [K=256, 768]: W_fx | W_comb
__device__ float g_bigb[768];
__device__ float g_st[Bg * Hh * Ss * Dd];   // slice_token accum  [B,H,S,D]
__device__ float g_sn[Bg * Hh * Ss];        // slice_norm accum   [B,H,S]
__device__ float g_ot[Bg * Hh * Ss * Dd];   // out_tok            [B,H,S,D]
__device__ float g_m1[Bg * 256 * 256];      // out_tok (.) W_out  [B, 256, 256]

// ---------------- prep: build fused weight [W_fx | W_x(.)W_slice] --------------
__global__ void prep_weights(const float* __restrict__ W_fx, const float* __restrict__ b_fx,
                             const float* __restrict__ W_x, const float* __restrict__ b_x,
                             const float* __restrict__ W_slice, const float* __restrict__ b_slice) {
    int k = blockIdx.x;          // 0..255
    int t = threadIdx.x;         // 0..255
    for (int c = t; c < 512; c += 256)
        g_bigW[k * 768 + c] = W_fx[k * 512 + c];
    {
        int h = t >> 5, s = t & 31;
        float a = 0.f;
        #pragma unroll
        for (int d = 0; d < 64; d++)
            a += W_x[k * 512 + h * 64 + d] * W_slice[d * 32 + s];
        g_bigW[k * 768 + 512 + t] = a;
    }
    if (k == 0) {
        for (int c = t; c < 512; c += 256) g_bigb[c] = b_fx[c];
        int h = t >> 5, s = t & 31;
        float bb = b_slice[s];
        #pragma unroll
        for (int d = 0; d < 64; d++)
            bb += b_x[h * 64 + d] * W_slice[d * 32 + s];
        g_bigb[512 + t] = bb;
    }
}

// ---------------- zero scatter accumulators ----------------
__global__ void zero_acc() {
    int i = blockIdx.x * blockDim.x + threadIdx.x;
    if (i < Bg * Hh * Ss * Dd) g_st[i] = 0.f;
    if (i < Bg * Hh * Ss) g_sn[i] = 0.f;
}

// -------- double-buffered 128x128x16 register-tiled SGEMM + bias --------------
// C[M,N] = A[M,K] @ B[K,N] + bias[N].  K mult of 16, N mult of 128, M guarded.
__global__ __launch_bounds__(256, 2) void gemm_bias_db(
    int M, int N, int K, int lda, int ldc,
    const float* __restrict__ A, const float* __restrict__ B,
    const float* __restrict__ bias, float* __restrict__ C)
{
    __shared__ float As[2][16][128];
    __shared__ float Bs[2][16][128];
    int tid = threadIdx.x;
    int bx = blockIdx.x, by = blockIdx.y;
    int tcol = tid & 15, trow = tid >> 4;
    int aRow = tid >> 2, aCol = (tid & 3) << 2;
    int bRow = tid >> 5, bCol = (tid & 31) << 2;

    float4 ra[2], rb[2], ran[2], rbn[2];

    // prologue: load tile 0
    #pragma unroll
    for (int i = 0; i < 2; i++) {
        int gr = by * 128 + aRow + i * 64;
        ra[i] = (gr < M) ? *(const float4*)&A[(size_t)gr * lda + aCol]
                         : make_float4(0.f, 0.f, 0.f, 0.f);
        rb[i] = *(const float4*)&B[(size_t)(bRow + i * 8) * N + bx * 128 + bCol];
    }
    #pragma unroll
    for (int i = 0; i < 2; i++) {
        int r = aRow + i * 64;
        As[0][aCol + 0][r] = ra[i].x; As[0][aCol + 1][r] = ra[i].y;
        As[0][aCol + 2][r] = ra[i].z; As[0][aCol + 3][r] = ra[i].w;
        *(float4*)&Bs[0][bRow + i * 8][bCol] = rb[i];
    }
    __syncthreads();

    float acc[8][8];
    #pragma unroll
    for (int i = 0; i < 8; i++)
        #pragma unroll
        for (int j = 0; j < 8; j++) acc[i][j] = 0.f;

    int nt = K / 16;
    for (int t = 0; t < nt; t++) {
        int cur = t & 1;
        if (t + 1 < nt) {
            int k0 = (t + 1) * 16;
            #pragma unroll
            for (int i = 0; i < 2; i++) {
                int gr = by * 128 + aRow + i * 64;
                ran[i] = (gr < M) ? *(const float4*)&A[(size_t)gr * lda + k0 + aCol]
                                  : make_float4(0.f, 0.f, 0.f, 0.f);
                rbn[i] = *(const float4*)&B[(size_t)(k0 + bRow + i * 8) * N + bx * 128 + bCol];
            }
        }
        #pragma unroll
        for (int kk = 0; kk < 16; kk++) {
            float a[8], b[8];
            #pragma unroll
            for (int i = 0; i < 8; i++) a[i] = As[cur][kk][trow * 8 + i];
            #pragma unroll
            for (int j = 0; j < 8; j++) b[j] = Bs[cur][kk][tcol * 8 + j];
            #pragma unroll
            for (int i = 0; i < 8; i++)
                #pragma unroll
                for (int j = 0; j < 8; j++) acc[i][j] += a[i] * b[j];
        }
        if (t + 1 < nt) {
            int nxt = cur ^ 1;
            #pragma unroll
            for (int i = 0; i < 2; i++) {
                int r = aRow + i * 64;
                As[nxt][aCol + 0][r] = ran[i].x; As[nxt][aCol + 1][r] = ran[i].y;
                As[nxt][aCol + 2][r] = ran[i].z; As[nxt][aCol + 3][r] = ran[i].w;
                *(float4*)&Bs[nxt][bRow + i * 8][bCol] = rbn[i];
            }
        }
        __syncthreads();
    }
    #pragma unroll
    for (int i = 0; i < 8; i++) {
        int gr = by * 128 + trow * 8 + i;
        if (gr >= M) continue;
        #pragma unroll
        for (int j = 0; j < 8; j += 4) {
            int gc = bx * 128 + tcol * 8 + j;
            float4 o;
            o.x = acc[i][j + 0] + bias[gc + 0];
            o.y = acc[i][j + 1] + bias[gc + 1];
            o.z = acc[i][j + 2] + bias[gc + 2];
            o.w = acc[i][j + 3] + bias[gc + 3];
            *(float4*)&C[(size_t)gr * ldc + gc] = o;
        }
    }
}

// ---------------- tempered softmax over S=32 (in-place on g_cat cols 512+) -----
__global__ void softmax_kernel(const float* __restrict__ temp, int total) {
    int gw = blockIdx.x * 8 + (threadIdx.x >> 5);   // gw = n*8 + h
    int lane = threadIdx.x & 31;
    if (gw >= total) return;
    int n = gw >> 3, h = gw & 7;
    float* p = &g_cat[(size_t)n * 768 + 512 + h * 32 + lane];
    float v = *p / temp[h];
    float m = v;
    #pragma unroll
    for (int o = 16; o; o >>= 1) m = fmaxf(m, __shfl_xor_sync(0xffffffffu, m, o));
    float e = expf(v - m);
    float s = e;
    #pragma unroll
    for (int o = 16; o; o >>= 1) s += __shfl_xor_sync(0xffffffffu, s, o);
    *p = e / s;
}

// ---------------- sync-free scatter: warp-per-h, lane-per-s -------------------
// slice_token[b,h,s,:] += w[n,h,s]*fx[n,h,:]; fx broadcast via shuffles.
__global__ void scatter_kernel(const int* __restrict__ batch, int N) {
    int h = threadIdx.x >> 5;     // warp id = head
    int lane = threadIdx.x & 31;  // slice
    int start = blockIdx.x * CHUNK;
    int end = min(start + CHUNK, N);

    float acc[64];
    #pragma unroll
    for (int d = 0; d < 64; d++) acc[d] = 0.f;
    float accn = 0.f;
    int cur_b = __ldg(&batch[start]);

    for (int n = start; n < end; n++) {
        int bn = __ldg(&batch[n]);
        if (bn != cur_b) {
            float* st = g_st + (((size_t)cur_b * 8 + h) * 32 + lane) * 64;
            #pragma unroll
            for (int d = 0; d < 64; d++) { atomicAdd(&st[d], acc[d]); acc[d] = 0.f; }
            atomicAdd(&g_sn[(cur_b * 8 + h) * 32 + lane], accn);
            accn = 0.f;
            cur_b = bn;
        }
        const float* row = &g_cat[(size_t)n * 768];
        float wv = row[512 + h * 32 + lane];
        float f0 = row[h * 64 + lane];
        float f1 = row[h * 64 + 32 + lane];
        accn += wv;
        #pragma unroll
        for (int d = 0; d < 32; d++) {
            acc[d]      += wv * __shfl_sync(0xffffffffu, f0, d);
            acc[d + 32] += wv * __shfl_sync(0xffffffffu, f1, d);
        }
    }
    float* st = g_st + (((size_t)cur_b * 8 + h) * 32 + lane) * 64;
    #pragma unroll
    for (int d = 0; d < 64; d++) atomicAdd(&st[d], acc[d]);
    atomicAdd(&g_sn[(cur_b * 8 + h) * 32 + lane], accn);
}

// ---------------- tiny attention over slice tokens, one block per (b,h) --------
__global__ void attention_kernel(const float* __restrict__ W_q, const float* __restrict__ W_k,
                                 const float* __restrict__ W_v) {
    int bh = blockIdx.x;   // b*8 + h
    __shared__ float st[32 * 64];
    __shared__ float q[32 * 64];
    __shared__ float kT[64 * 33];
    __shared__ float v[32 * 64];
    __shared__ float attn[32 * 32];
    int tid = threadIdx.x;
    const float* base = g_st + (size_t)bh * 2048;
    const float* nrm = g_sn + bh * 32;

    for (int i = tid; i < 2048; i += 256) {
        int s = i >> 6;
        st[i] = base[i] / (nrm[s] + 1e-5f);
    }
    __syncthreads();
    for (int i = tid; i < 2048; i += 256) {
        int s = i >> 6, e = i & 63;
        float aq = 0.f, ak = 0.f, av = 0.f;
        #pragma unroll
        for (int d = 0; d < 64; d++) {
            float sv = st[s * 64 + d];
            aq += sv * W_q[d * 64 + e];
            ak += sv * W_k[d * 64 + e];
            av += sv * W_v[d * 64 + e];
        }
        q[i] = aq; kT[e * 33 + s] = ak; v[i] = av;
    }
    __syncthreads();
    for (int i = tid; i < 1024; i += 256) {
        int s = i >> 5, t = i & 31;
        float a = 0.f;
        #pragma unroll
        for (int d = 0; d < 64; d++) a += q[s * 64 + d] * kT[d * 33 + t];
        attn[i] = a * 0.125f;
    }
    __syncthreads();
    int warp = tid >> 5, lane = tid & 31;
    for (int r = warp; r < 32; r += 8) {
        float val = attn[r * 32 + lane];
        float m = val;
        #pragma unroll
        for (int o = 16; o; o >>= 1) m = fmaxf(m, __shfl_xor_sync(0xffffffffu, m, o));
        float e = expf(val - m);
        float ssum = e;
        #pragma unroll
        for (int o = 16; o; o >>= 1) ssum += __shfl_xor_sync(0xffffffffu, ssum, o);
        attn[r * 32 + lane] = e / ssum;
    }
    __syncthreads();
    float* ob = g_ot + (size_t)bh * 2048;
    for (int i = tid; i < 2048; i += 256) {
        int s = i >> 6, d = i & 63;
        float a = 0.f;
        #pragma unroll
        for (int t = 0; t < 32; t++) a += attn[s * 32 + t] * v[t * 64 + d];
        ob[i] = a;
    }
}

// ---------------- fold out_tok with W_out: M1[b][h*32+s][j] ----------------
__global__ void build_m1(const float* __restrict__ W_out) {
    int bh = blockIdx.x;
    int h = bh & 7, b = bh >> 3;
    __shared__ float ot[2048];
    int tid = threadIdx.x;
    for (int i = tid; i < 2048; i += 256) ot[i] = g_ot[(size_t)bh * 2048 + i];
    __syncthreads();
    for (int i = tid; i < 8192; i += 256) {
        int s = i >> 8, j = i & 255;
        float a = 0.f;
        #pragma unroll
        for (int d = 0; d < 64; d++)
            a += ot[s * 64 + d] * W_out[(h * 64 + d) * 256 + j];
        g_m1[((size_t)b * 256 + h * 32 + s) * 256 + j] = a;
    }
}

// ------- final: out[n,:] = w[n,:] @ M1[batch[n]] + b_out (double-buffered) -----
__global__ __launch_bounds__(256, 2) void final_gemm_db(
    int M, const int* __restrict__ batch,
    const float* __restrict__ bias, float* __restrict__ C)
{
    const int K = 256, N = 256;
    __shared__ float As[2][16][128];
    __shared__ float Bs[2][16][128];
    __shared__ int sb[128];
    int tid = threadIdx.x;
    int bx = blockIdx.x, by = blockIdx.y;
    int row0 = by * 128;
    int rows = min(128, M - row0);
    for (int i = tid; i < 128; i += 256) sb[i] = (i < rows) ? batch[row0 + i] : -1;
    __syncthreads();
    int b_first = sb[0], b_last = sb[rows - 1];
    int tcol = tid & 15, trow = tid >> 4;
    int aRow = tid >> 2, aCol = (tid & 3) << 2;
    int bRow = tid >> 5, bCol = (tid & 31) << 2;

    for (int bb = b_first; bb <= b_last; bb++) {
        const float* B = g_m1 + (size_t)bb * 256 * 256;
        float4 ra[2], rb[2], ran[2], rbn[2];
        #pragma unroll
        for (int i = 0; i < 2; i++) {
            int gr = row0 + aRow + i * 64;
            ra[i] = (gr < M) ? *(const float4*)&g_cat[(size_t)gr * 768 + 512 + aCol]
                             : make_float4(0.f, 0.f, 0.f, 0.f);
            rb[i] = *(const float4*)&B[(size_t)(bRow + i * 8) * N + bx * 128 + bCol];
        }
        #pragma unroll
        for (int i = 0; i < 2; i++) {
            int r = aRow + i * 64;
            As[0][aCol + 0][r] = ra[i].x; As[0][aCol + 1][r] = ra[i].y;
            As[0][aCol + 2][r] = ra[i].z; As[0][aCol + 3][r] = ra[i].w;
            *(float4*)&Bs[0][bRow + i * 8][bCol] = rb[i];
        }
        __syncthreads();

        float acc[8][8];
        #pragma unroll
        for (int i = 0; i < 8; i++)
            #pragma unroll
            for (int j = 0; j < 8; j++) acc[i][j] = 0.f;

        const int nt = K / 16;
        for (int t = 0; t < nt; t++) {
            int cur = t & 1;
            if (t + 1 < nt) {
                int k0 = (t + 1) * 16;
                #pragma unroll
                for (int i = 0; i < 2; i++) {
                    int gr = row0 + aRow + i * 64;
                    ran[i] = (gr < M) ? *(const float4*)&g_cat[(size_t)gr * 768 + 512 + k0 + aCol]
                                      : make_float4(0.f, 0.f, 0.f, 0.f);
                    rbn[i] = *(const float4*)&B[(size_t)(k0 + bRow + i * 8) * N + bx * 128 + bCol];
                }
            }
            #pragma unroll
            for (int kk = 0; kk < 16; kk++) {
                float a[8], b[8];
                #pragma unroll
                for (int i = 0; i < 8; i++) a[i] = As[cur][kk][trow * 8 + i];
                #pragma unroll
                for (int j = 0; j < 8; j++) b[j] = Bs[cur][kk][tcol * 8 + j];
                #pragma unroll
                for (int i = 0; i < 8; i++)
                    #pragma unroll
                    for (int j = 0; j < 8; j++) acc[i][j] += a[i] * b[j];
            }
            if (t + 1 < nt) {
                int nxt = cur ^ 1;
                #pragma unroll
                for (int i = 0; i < 2; i++) {
                    int r = aRow + i * 64;
                    As[nxt][aCol + 0][r] = ran[i].x; As[nxt][aCol + 1][r] = ran[i].y;
                    As[nxt][aCol + 2][r] = ran[i].z; As[nxt][aCol + 3][r] = ran[i].w;
                    *(float4*)&Bs[nxt][bRow + i * 8][bCol] = rbn[i];
                }
            }
            __syncthreads();
        }
        #pragma unroll
        for (int i = 0; i < 8; i++) {
            int r = trow * 8 + i;
            int gr = row0 + r;
            if (gr < M && sb[r] == bb) {
                #pragma unroll
                for (int j = 0; j < 8; j += 4) {
                    int gc = bx * 128 + tcol * 8 + j;
                    float4 o;
                    o.x = acc[i][j + 0] + bias[gc + 0];
                    o.y = acc[i][j + 1] + bias[gc + 1];
                    o.z = acc[i][j + 2] + bias[gc + 2];
                    o.w = acc[i][j + 3] + bias[gc + 3];
                    *(float4*)&C[(size_t)gr * 256 + gc] = o;
                }
            }
        }
        __syncthreads();
    }
}

// ---------------- launch ----------------
extern "C" void kernel_launch(void* const* d_in, const int* in_sizes, int n_in,
                              void* d_out, int out_size) {
    const float* x       = (const float*)d_in[0];
    const int*   batch   = (const int*)d_in[1];
    const float* W_fx    = (const float*)d_in[2];
    const float* b_fx    = (const float*)d_in[3];
    const float* W_x     = (const float*)d_in[4];
    const float* b_x     = (const float*)d_in[5];
    const float* W_slice = (const float*)d_in[6];
    const float* b_slice = (const float*)d_in[7];
    const float* gtemp   = (const float*)d_in[8];
    const float* W_q     = (const float*)d_in[9];
    const float* W_k     = (const float*)d_in[10];
    const float* W_v     = (const float*)d_in[11];
    const float* W_out   = (const float*)d_in[12];
    const float* b_out   = (const float*)d_in[13];
    float* out = (float*)d_out;

    int n = in_sizes[1];
    int rowBlocks = (n + 127) / 128;

    float *p_cat, *p_bigW, *p_bigb;
    cudaGetSymbolAddress((void**)&p_cat, g_cat);
    cudaGetSymbolAddress((void**)&p_bigW, g_bigW);
    cudaGetSymbolAddress((void**)&p_bigb, g_bigb);

    // 1. build fused weight/bias
    prep_weights<<<256, 256>>>(W_fx, b_fx, W_x, b_x, W_slice, b_slice);
    // 2. zero scatter accumulators
    zero_acc<<<512, 256>>>();
    // 3. fused GEMM: [fx | logits] = x @ bigW + bigb     [N,768]
    gemm_bias_db<<<dim3(6, rowBlocks), 256>>>(n, 768, 256, 256, 768, x, p_bigW, p_bigb, p_cat);
    // 4. tempered softmax over S (in place, cols 512..767)
    softmax_kernel<<<n, 256>>>(gtemp, n * 8);
    // 5. scatter-add pooling (sync-free, shuffle broadcast)
    scatter_kernel<<<rowBlocks, 256>>>(batch, n);
    // 6. tiny attention over slice tokens
    attention_kernel<<<64, 256>>>(W_q, W_k, W_v);
    // 7. fold out_tok with W_out
    build_m1<<<64, 256>>>(W_out);
    // 8. out = w @ M1[batch] + b_out
    final_gemm_db<<<dim3(2, rowBlocks), 256>>>(n, batch, b_out, out);
}

// round 7
// speedup vs baseline: 1.4036x; 1.2519x over previous
#include <cuda_runtime.h>
#include <cuda_bf16.h>
#include <cstdint>

#define Hh 8
#define Dd 64
#define Ss 32
#define Bg 8
#define MAXN 30720
#define CHUNK 128
#define PADK 40   // bf16 row stride in smem (80B) -> conflict-free ldmatrix

// ---------------- scratch (static device globals; no allocation) ----------------
__device__ float g_cat[MAXN * 768];         // [N, 768]: cols 0..511 fx, 512..767 w
__device__ float g_bigWt[768 * 256];        // fused weight, TRANSPOSED [768, 256]
__device__ float g_bigb[768];
__device__ float g_st[Bg * Hh * Ss * Dd];   // slice_token accum  [B,H,S,D]
__device__ float g_sn[Bg * Hh * Ss];        // slice_norm accum   [B,H,S]
__device__ float g_ot[Bg * Hh * Ss * Dd];   // out_tok            [B,H,S,D]
__device__ float g_m1[Bg * 256 * 256];      // out_tok (.) W_out  [B, 256, 256]

__device__ __forceinline__ uint32_t smem_u32(const void* p) {
    uint32_t a;
    asm("{ .reg .u64 t; cvta.to.shared.u64 t, %1; cvt.u32.u64 %0, t; }" : "=r"(a) : "l"(p));
    return a;
}
__device__ __forceinline__ uint16_t bfbits(float f) {
    return __bfloat16_as_ushort(__float2bfloat16(f));
}
__device__ __forceinline__ void ldsm_x4(uint32_t* r, uint32_t addr) {
    asm volatile("ldmatrix.sync.aligned.m8n8.x4.shared.b16 {%0,%1,%2,%3}, [%4];"
        : "=r"(r[0]), "=r"(r[1]), "=r"(r[2]), "=r"(r[3]) : "r"(addr));
}
__device__ __forceinline__ void mma_bf16(float* d, const uint32_t* a, const uint32_t* b) {
    asm volatile("mma.sync.aligned.m16n8k16.row.col.f32.bf16.bf16.f32 "
        "{%0,%1,%2,%3}, {%4,%5,%6,%7}, {%8,%9}, {%0,%1,%2,%3};"
        : "+f"(d[0]), "+f"(d[1]), "+f"(d[2]), "+f"(d[3])
        : "r"(a[0]), "r"(a[1]), "r"(a[2]), "r"(a[3]), "r"(b[0]), "r"(b[1]));
}
// pack fp32x4 -> bf16 hi pair + lo pair (2x u32 each)
__device__ __forceinline__ void split4(float4 v, uint32_t& h0, uint32_t& h1,
                                       uint32_t& l0, uint32_t& l1) {
    uint16_t hx = bfbits(v.x), hy = bfbits(v.y), hz = bfbits(v.z), hw = bfbits(v.w);
    h0 = (uint32_t)hx | ((uint32_t)hy << 16);
    h1 = (uint32_t)hz | ((uint32_t)hw << 16);
    float lx = v.x - __bfloat162float(__ushort_as_bfloat16(hx));
    float ly = v.y - __bfloat162float(__ushort_as_bfloat16(hy));
    float lz = v.z - __bfloat162float(__ushort_as_bfloat16(hz));
    float lw = v.w - __bfloat162float(__ushort_as_bfloat16(hw));
    l0 = (uint32_t)bfbits(lx) | ((uint32_t)bfbits(ly) << 16);
    l1 = (uint32_t)bfbits(lz) | ((uint32_t)bfbits(lw) << 16);
}

// ---------------- prep: fused transposed weight [W_fx | W_x(.)W_slice]^T -------
__global__ void prep_weights(const float* __restrict__ W_fx, const float* __restrict__ b_fx,
                             const float* __restrict__ W_x, const float* __restrict__ b_x,
                             const float* __restrict__ W_slice, const float* __restrict__ b_slice) {
    int k = blockIdx.x;          // 0..255
    int t = threadIdx.x;         // 0..255
    for (int c = t; c < 512; c += 256)
        g_bigWt[(size_t)c * 256 + k] = W_fx[k * 512 + c];
    {
        int h = t >> 5, s = t & 31;
        float a = 0.f;
        #pragma unroll
        for (int d = 0; d < 64; d++)
            a += W_x[k * 512 + h * 64 + d] * W_slice[d * 32 + s];
        g_bigWt[(size_t)(512 + t) * 256 + k] = a;
    }
    if (k == 0) {
        for (int c = t; c < 512; c += 256) g_bigb[c] = b_fx[c];
        int h = t >> 5, s = t & 31;
        float bb = b_slice[s];
        #pragma unroll
        for (int d = 0; d < 64; d++)
            bb += b_x[h * 64 + d] * W_slice[d * 32 + s];
        g_bigb[512 + t] = bb;
    }
}

__global__ void zero_acc() {
    int i = blockIdx.x * blockDim.x + threadIdx.x;
    if (i < Bg * Hh * Ss * Dd) g_st[i] = 0.f;
    if (i < Bg * Hh * Ss) g_sn[i] = 0.f;
}

// ========== split-bf16 HMMA fused GEMM: g_cat = x @ bigW + bias ===============
// Block tile 128x128, K=256 in 8 chunks of 32. 8 warps = 4(m) x 2(n), warp 32x64.
__global__ __launch_bounds__(256, 2) void fused_gemm_mma(int M, const float* __restrict__ x) {
    __shared__ __align__(16) uint32_t Ahi[128 * PADK / 2];
    __shared__ __align__(16) uint32_t Alo[128 * PADK / 2];
    __shared__ __align__(16) uint32_t Bhi[128 * PADK / 2];
    __shared__ __align__(16) uint32_t Blo[128 * PADK / 2];

    int tid = threadIdx.x, wid = tid >> 5, lane = tid & 31;
    int bx = blockIdx.x, by = blockIdx.y;
    int row0 = by * 128, n0 = bx * 128;
    int warp_m = (wid & 3) * 32, warp_n = (wid >> 2) * 64;

    float acc[2][8][4];
    #pragma unroll
    for (int mi = 0; mi < 2; mi++)
        #pragma unroll
        for (int ni = 0; ni < 8; ni++)
            #pragma unroll
            for (int j = 0; j < 4; j++) acc[mi][ni][j] = 0.f;

    // ldmatrix per-lane offsets (bf16 element units)
    int a_row = ((lane >> 3) & 1) * 8 + (lane & 7);
    int a_col = (lane >> 4) * 8;
    int b_row = ((lane >> 4) & 1) * 8 + (lane & 7);
    int b_col = ((lane >> 3) & 1) * 8;

    uint32_t sAhi = smem_u32(Ahi), sAlo = smem_u32(Alo);
    uint32_t sBhi = smem_u32(Bhi), sBlo = smem_u32(Blo);

    int lrow = tid >> 1;                 // 0..127
    int lc0 = (tid & 1) * 16;            // 0 or 16

    for (int c = 0; c < 8; c++) {
        int k0 = c * 32;
        // ---- A chunk 128x32 fp32 -> bf16 hi/lo ----
        {
            int gr = row0 + lrow;
            const float* src = x + (size_t)gr * 256 + k0 + lc0;
            uint32_t* dh = &Ahi[(lrow * PADK + lc0) >> 1];
            uint32_t* dl = &Alo[(lrow * PADK + lc0) >> 1];
            #pragma unroll
            for (int i = 0; i < 4; i++) {
                float4 v = (gr < M) ? *(const float4*)(src + i * 4)
                                    : make_float4(0.f, 0.f, 0.f, 0.f);
                uint32_t h0, h1, l0, l1;
                split4(v, h0, h1, l0, l1);
                dh[i * 2] = h0; dh[i * 2 + 1] = h1;
                dl[i * 2] = l0; dl[i * 2 + 1] = l1;
            }
        }
        // ---- B chunk 128x32 (rows n0..n0+127 of g_bigWt) ----
        {
            const float* src = g_bigWt + (size_t)(n0 + lrow) * 256 + k0 + lc0;
            uint32_t* dh = &Bhi[(lrow * PADK + lc0) >> 1];
            uint32_t* dl = &Blo[(lrow * PADK + lc0) >> 1];
            #pragma unroll
            for (int i = 0; i < 4; i++) {
                float4 v = *(const float4*)(src + i * 4);
                uint32_t h0, h1, l0, l1;
                split4(v, h0, h1, l0, l1);
                dh[i * 2] = h0; dh[i * 2 + 1] = h1;
                dl[i * 2] = l0; dl[i * 2 + 1] = l1;
            }
        }
        __syncthreads();

        #pragma unroll
        for (int p = 0; p < 3; p++) {
            uint32_t sA = (p == 2) ? sAlo : sAhi;
            uint32_t sB = (p == 1) ? sBlo : sBhi;
            #pragma unroll
            for (int ks = 0; ks < 2; ks++) {
                int kb = ks * 16;
                uint32_t af[2][4];
                #pragma unroll
                for (int mi = 0; mi < 2; mi++)
                    ldsm_x4(af[mi], sA + ((warp_m + mi * 16 + a_row) * PADK + kb + a_col) * 2);
                uint32_t bfr[8][2];
                #pragma unroll
                for (int nj = 0; nj < 4; nj++) {
                    uint32_t r[4];
                    ldsm_x4(r, sB + ((warp_n + nj * 16 + b_row) * PADK + kb + b_col) * 2);
                    bfr[nj * 2][0] = r[0]; bfr[nj * 2][1] = r[1];
                    bfr[nj * 2 + 1][0] = r[2]; bfr[nj * 2 + 1][1] = r[3];
                }
                #pragma unroll
                for (int mi = 0; mi < 2; mi++)
                    #pragma unroll
                    for (int ni = 0; ni < 8; ni++)
                        mma_bf16(acc[mi][ni], af[mi], bfr[ni]);
            }
        }
        __syncthreads();
    }

    // ---- epilogue: add bias, store fp32 to g_cat ----
    int r_in = lane >> 2, c_in = (lane & 3) * 2;
    #pragma unroll
    for (int mi = 0; mi < 2; mi++) {
        #pragma unroll
        for (int ni = 0; ni < 8; ni++) {
            int gc = n0 + warp_n + ni * 8 + c_in;
            float b0 = g_bigb[gc], b1 = g_bigb[gc + 1];
            int gr0 = row0 + warp_m + mi * 16 + r_in;
            if (gr0 < M) {
                float2 o = make_float2(acc[mi][ni][0] + b0, acc[mi][ni][1] + b1);
                *(float2*)&g_cat[(size_t)gr0 * 768 + gc] = o;
            }
            int gr1 = gr0 + 8;
            if (gr1 < M) {
                float2 o = make_float2(acc[mi][ni][2] + b0, acc[mi][ni][3] + b1);
                *(float2*)&g_cat[(size_t)gr1 * 768 + gc] = o;
            }
        }
    }
}

// ---------------- tempered softmax over S=32 (in-place, cols 512+) -------------
__global__ void softmax_kernel(const float* __restrict__ temp, int total) {
    int gw = blockIdx.x * 8 + (threadIdx.x >> 5);
    int lane = threadIdx.x & 31;
    if (gw >= total) return;
    int n = gw >> 3, h = gw & 7;
    float* p = &g_cat[(size_t)n * 768 + 512 + h * 32 + lane];
    float v = *p / temp[h];
    float m = v;
    #pragma unroll
    for (int o = 16; o; o >>= 1) m = fmaxf(m, __shfl_xor_sync(0xffffffffu, m, o));
    float e = __expf(v - m);
    float s = e;
    #pragma unroll
    for (int o = 16; o; o >>= 1) s += __shfl_xor_sync(0xffffffffu, s, o);
    *p = e / s;
}

// ---------------- sync-free scatter: warp-per-h, lane-per-s -------------------
__global__ void scatter_kernel(const int* __restrict__ batch, int N) {
    int h = threadIdx.x >> 5;
    int lane = threadIdx.x & 31;
    int start = blockIdx.x * CHUNK;
    int end = min(start + CHUNK, N);

    float acc[64];
    #pragma unroll
    for (int d = 0; d < 64; d++) acc[d] = 0.f;
    float accn = 0.f;
    int cur_b = __ldg(&batch[start]);

    for (int n = start; n < end; n++) {
        int bn = __ldg(&batch[n]);
        if (bn != cur_b) {
            float* st = g_st + (((size_t)cur_b * 8 + h) * 32 + lane) * 64;
            #pragma unroll
            for (int d = 0; d < 64; d++) { atomicAdd(&st[d], acc[d]); acc[d] = 0.f; }
            atomicAdd(&g_sn[(cur_b * 8 + h) * 32 + lane], accn);
            accn = 0.f;
            cur_b = bn;
        }
        const float* row = &g_cat[(size_t)n * 768];
        float wv = row[512 + h * 32 + lane];
        float f0 = row[h * 64 + lane];
        float f1 = row[h * 64 + 32 + lane];
        accn += wv;
        #pragma unroll
        for (int d = 0; d < 32; d++) {
            acc[d]      += wv * __shfl_sync(0xffffffffu, f0, d);
            acc[d + 32] += wv * __shfl_sync(0xffffffffu, f1, d);
        }
    }
    float* st = g_st + (((size_t)cur_b * 8 + h) * 32 + lane) * 64;
    #pragma unroll
    for (int d = 0; d < 64; d++) atomicAdd(&st[d], acc[d]);
    atomicAdd(&g_sn[(cur_b * 8 + h) * 32 + lane], accn);
}

// ---------------- tiny attention over slice tokens, one block per (b,h) --------
__global__ void attention_kernel(const float* __restrict__ W_q, const float* __restrict__ W_k,
                                 const float* __restrict__ W_v) {
    int bh = blockIdx.x;
    __shared__ float st[32 * 64];
    __shared__ float q[32 * 64];
    __shared__ float kT[64 * 33];
    __shared__ float v[32 * 64];
    __shared__ float attn[32 * 32];
    int tid = threadIdx.x;
    const float* base = g_st + (size_t)bh * 2048;
    const float* nrm = g_sn + bh * 32;

    for (int i = tid; i < 2048; i += 256) {
        int s = i >> 6;
        st[i] = base[i] / (nrm[s] + 1e-5f);
    }
    __syncthreads();
    for (int i = tid; i < 2048; i += 256) {
        int s = i >> 6, e = i & 63;
        float aq = 0.f, ak = 0.f, av = 0.f;
        #pragma unroll
        for (int d = 0; d < 64; d++) {
            float sv = st[s * 64 + d];
            aq += sv * W_q[d * 64 + e];
            ak += sv * W_k[d * 64 + e];
            av += sv * W_v[d * 64 + e];
        }
        q[i] = aq; kT[e * 33 + s] = ak; v[i] = av;
    }
    __syncthreads();
    for (int i = tid; i < 1024; i += 256) {
        int s = i >> 5, t = i & 31;
        float a = 0.f;
        #pragma unroll
        for (int d = 0; d < 64; d++) a += q[s * 64 + d] * kT[d * 33 + t];
        attn[i] = a * 0.125f;
    }
    __syncthreads();
    int warp = tid >> 5, lane = tid & 31;
    for (int r = warp; r < 32; r += 8) {
        float val = attn[r * 32 + lane];
        float m = val;
        #pragma unroll
        for (int o = 16; o; o >>= 1) m = fmaxf(m, __shfl_xor_sync(0xffffffffu, m, o));
        float e = __expf(val - m);
        float ssum = e;
        #pragma unroll
        for (int o = 16; o; o >>= 1) ssum += __shfl_xor_sync(0xffffffffu, ssum, o);
        attn[r * 32 + lane] = e / ssum;
    }
    __syncthreads();
    float* ob = g_ot + (size_t)bh * 2048;
    for (int i = tid; i < 2048; i += 256) {
        int s = i >> 6, d = i & 63;
        float a = 0.f;
        #pragma unroll
        for (int t = 0; t < 32; t++) a += attn[s * 32 + t] * v[t * 64 + d];
        ob[i] = a;
    }
}

// ---------------- fold out_tok with W_out: M1[b][h*32+s][j] ----------------
__global__ void build_m1(const float* __restrict__ W_out) {
    int bh = blockIdx.x;
    int h = bh & 7, b = bh >> 3;
    __shared__ float ot[2048];
    int tid = threadIdx.x;
    for (int i = tid; i < 2048; i += 256) ot[i] = g_ot[(size_t)bh * 2048 + i];
    __syncthreads();
    for (int i = tid; i < 8192; i += 256) {
        int s = i >> 8, j = i & 255;
        float a = 0.f;
        #pragma unroll
        for (int d = 0; d < 64; d++)
            a += ot[s * 64 + d] * W_out[(h * 64 + d) * 256 + j];
        g_m1[((size_t)b * 256 + h * 32 + s) * 256 + j] = a;
    }
}

// ------- final: out[n,:] = w[n,:] @ M1[batch[n]] + b_out (double-buffered) -----
__global__ __launch_bounds__(256, 2) void final_gemm_db(
    int M, const int* __restrict__ batch,
    const float* __restrict__ bias, float* __restrict__ C)
{
    const int K = 256, N = 256;
    __shared__ float As[2][16][128];
    __shared__ float Bs[2][16][128];
    __shared__ int sb[128];
    int tid = threadIdx.x;
    int bx = blockIdx.x, by = blockIdx.y;
    int row0 = by * 128;
    int rows = min(128, M - row0);
    for (int i = tid; i < 128; i += 256) sb[i] = (i < rows) ? batch[row0 + i] : -1;
    __syncthreads();
    int b_first = sb[0], b_last = sb[rows - 1];
    int tcol = tid & 15, trow = tid >> 4;
    int aRow = tid >> 2, aCol = (tid & 3) << 2;
    int bRow = tid >> 5, bCol = (tid & 31) << 2;

    for (int bb = b_first; bb <= b_last; bb++) {
        const float* B = g_m1 + (size_t)bb * 256 * 256;
        float4 ra[2], rb[2], ran[2], rbn[2];
        #pragma unroll
        for (int i = 0; i < 2; i++) {
            int gr = row0 + aRow + i * 64;
            ra[i] = (gr < M) ? *(const float4*)&g_cat[(size_t)gr * 768 + 512 + aCol]
                             : make_float4(0.f, 0.f, 0.f, 0.f);
            rb[i] = *(const float4*)&B[(size_t)(bRow + i * 8) * N + bx * 128 + bCol];
        }
        #pragma unroll
        for (int i = 0; i < 2; i++) {
            int r = aRow + i * 64;
            As[0][aCol + 0][r] = ra[i].x; As[0][aCol + 1][r] = ra[i].y;
            As[0][aCol + 2][r] = ra[i].z; As[0][aCol + 3][r] = ra[i].w;
            *(float4*)&Bs[0][bRow + i * 8][bCol] = rb[i];
        }
        __syncthreads();

        float acc[8][8];
        #pragma unroll
        for (int i = 0; i < 8; i++)
            #pragma unroll
            for (int j = 0; j < 8; j++) acc[i][j] = 0.f;

        const int nt = K / 16;
        for (int t = 0; t < nt; t++) {
            int cur = t & 1;
            if (t + 1 < nt) {
                int k0 = (t + 1) * 16;
                #pragma unroll
                for (int i = 0; i < 2; i++) {
                    int gr = row0 + aRow + i * 64;
                    ran[i] = (gr < M) ? *(const float4*)&g_cat[(size_t)gr * 768 + 512 + k0 + aCol]
                                      : make_float4(0.f, 0.f, 0.f, 0.f);
                    rbn[i] = *(const float4*)&B[(size_t)(k0 + bRow + i * 8) * N + bx * 128 + bCol];
                }
            }
            #pragma unroll
            for (int kk = 0; kk < 16; kk++) {
                float a[8], b[8];
                #pragma unroll
                for (int i = 0; i < 8; i++) a[i] = As[cur][kk][trow * 8 + i];
                #pragma unroll
                for (int j = 0; j < 8; j++) b[j] = Bs[cur][kk][tcol * 8 + j];
                #pragma unroll
                for (int i = 0; i < 8; i++)
                    #pragma unroll
                    for (int j = 0; j < 8; j++) acc[i][j] += a[i] * b[j];
            }
            if (t + 1 < nt) {
                int nxt = cur ^ 1;
                #pragma unroll
                for (int i = 0; i < 2; i++) {
                    int r = aRow + i * 64;
                    As[nxt][aCol + 0][r] = ran[i].x; As[nxt][aCol + 1][r] = ran[i].y;
                    As[nxt][aCol + 2][r] = ran[i].z; As[nxt][aCol + 3][r] = ran[i].w;
                    *(float4*)&Bs[nxt][bRow + i * 8][bCol] = rbn[i];
                }
            }
            __syncthreads();
        }
        #pragma unroll
        for (int i = 0; i < 8; i++) {
            int r = trow * 8 + i;
            int gr = row0 + r;
            if (gr < M && sb[r] == bb) {
                #pragma unroll
                for (int j = 0; j < 8; j += 4) {
                    int gc = bx * 128 + tcol * 8 + j;
                    float4 o;
                    o.x = acc[i][j + 0] + bias[gc + 0];
                    o.y = acc[i][j + 1] + bias[gc + 1];
                    o.z = acc[i][j + 2] + bias[gc + 2];
                    o.w = acc[i][j + 3] + bias[gc + 3];
                    *(float4*)&C[(size_t)gr * 256 + gc] = o;
                }
            }
        }
        __syncthreads();
    }
}

// ---------------- launch ----------------
extern "C" void kernel_launch(void* const* d_in, const int* in_sizes, int n_in,
                              void* d_out, int out_size) {
    const float* x       = (const float*)d_in[0];
    const int*   batch   = (const int*)d_in[1];
    const float* W_fx    = (const float*)d_in[2];
    const float* b_fx    = (const float*)d_in[3];
    const float* W_x     = (const float*)d_in[4];
    const float* b_x     = (const float*)d_in[5];
    const float* W_slice = (const float*)d_in[6];
    const float* b_slice = (const float*)d_in[7];
    const float* gtemp   = (const float*)d_in[8];
    const float* W_q     = (const float*)d_in[9];
    const float* W_k     = (const float*)d_in[10];
    const float* W_v     = (const float*)d_in[11];
    const float* W_out   = (const float*)d_in[12];
    const float* b_out   = (const float*)d_in[13];
    float* out = (float*)d_out;

    int n = in_sizes[1];
    int rowBlocks = (n + 127) / 128;

    // 1. build fused transposed weight/bias
    prep_weights<<<256, 256>>>(W_fx, b_fx, W_x, b_x, W_slice, b_slice);
    // 2. zero scatter accumulators
    zero_acc<<<512, 256>>>();
    // 3. split-bf16 HMMA fused GEMM: [fx | logits] = x @ bigW + bigb
    fused_gemm_mma<<<dim3(6, rowBlocks), 256>>>(n, x);
    // 4. tempered softmax over S
    softmax_kernel<<<n, 256>>>(gtemp, n * 8);
    // 5. scatter-add pooling
    scatter_kernel<<<rowBlocks, 256>>>(batch, n);
    // 6. tiny attention over slice tokens
    attention_kernel<<<64, 256>>>(W_q, W_k, W_v);
    // 7. fold out_tok with W_out
    build_m1<<<64, 256>>>(W_out);
    // 8. out = w @ M1[batch] + b_out
    final_gemm_db<<<dim3(2, rowBlocks), 256>>>(n, batch, b_out, out);
}

// round 10
// speedup vs baseline: 1.6090x; 1.1463x over previous
#include <cuda_runtime.h>
#include <cuda_bf16.h>
#include <cstdint>

#define Hh 8
#define Dd 64
#define Ss 32
#define Bg 8
#define MAXN 30720
#define CHUNK 128
#define PADK 40   // bf16 row stride in smem (80B) -> conflict-free ldmatrix

// ---------------- scratch (static device globals; no allocation) ----------------
__device__ float g_cat[MAXN * 768];         // [N, 768]: cols 0..511 fx, 512..767 w (fp32)
__device__ __nv_bfloat16 g_bWh[768 * 256];  // fused weight bf16 hi [n=768][k=256]
__device__ __nv_bfloat16 g_bWl[768 * 256];  // fused weight bf16 lo
__device__ __nv_bfloat16 g_wh[MAXN * 256];  // softmaxed w bf16 hi [n][k=256]
__device__ __nv_bfloat16 g_wl[MAXN * 256];  // softmaxed w bf16 lo
__device__ float g_bigb[768];
__device__ float g_st[Bg * Hh * Ss * Dd];   // slice_token accum  [B,H,S,D]
__device__ float g_sn[Bg * Hh * Ss];        // slice_norm accum   [B,H,S]
__device__ float g_ot[Bg * Hh * Ss * Dd];   // out_tok            [B,H,S,D]
__device__ __nv_bfloat16 g_m1h[Bg * 256 * 256]; // M1 transposed bf16 hi [b][j=256][hs=256]
__device__ __nv_bfloat16 g_m1l[Bg * 256 * 256]; // M1 transposed bf16 lo

__device__ __forceinline__ uint32_t smem_u32(const void* p) {
    uint32_t a;
    asm("{ .reg .u64 t; cvta.to.shared.u64 t, %1; cvt.u32.u64 %0, t; }" : "=r"(a) : "l"(p));
    return a;
}
__device__ __forceinline__ uint16_t bfbits(float f) {
    return __bfloat16_as_ushort(__float2bfloat16(f));
}
__device__ __forceinline__ void ldsm_x4(uint32_t* r, uint32_t addr) {
    asm volatile("ldmatrix.sync.aligned.m8n8.x4.shared.b16 {%0,%1,%2,%3}, [%4];"
        : "=r"(r[0]), "=r"(r[1]), "=r"(r[2]), "=r"(r[3]) : "r"(addr));
}
__device__ __forceinline__ void mma_bf16(float* d, const uint32_t* a, const uint32_t* b) {
    asm volatile("mma.sync.aligned.m16n8k16.row.col.f32.bf16.bf16.f32 "
        "{%0,%1,%2,%3}, {%4,%5,%6,%7}, {%8,%9}, {%0,%1,%2,%3};"
        : "+f"(d[0]), "+f"(d[1]), "+f"(d[2]), "+f"(d[3])
        : "r"(a[0]), "r"(a[1]), "r"(a[2]), "r"(a[3]), "r"(b[0]), "r"(b[1]));
}
__device__ __forceinline__ void split4(float4 v, uint32_t& h0, uint32_t& h1,
                                       uint32_t& l0, uint32_t& l1) {
    uint16_t hx = bfbits(v.x), hy = bfbits(v.y), hz = bfbits(v.z), hw = bfbits(v.w);
    h0 = (uint32_t)hx | ((uint32_t)hy << 16);
    h1 = (uint32_t)hz | ((uint32_t)hw << 16);
    float lx = v.x - __bfloat162float(__ushort_as_bfloat16(hx));
    float ly = v.y - __bfloat162float(__ushort_as_bfloat16(hy));
    float lz = v.z - __bfloat162float(__ushort_as_bfloat16(hz));
    float lw = v.w - __bfloat162float(__ushort_as_bfloat16(hw));
    l0 = (uint32_t)bfbits(lx) | ((uint32_t)bfbits(ly) << 16);
    l1 = (uint32_t)bfbits(lz) | ((uint32_t)bfbits(lw) << 16);
}
__device__ __forceinline__ void split_store(float v, __nv_bfloat16* ph, __nv_bfloat16* pl) {
    __nv_bfloat16 h = __float2bfloat16(v);
    *ph = h;
    *pl = __float2bfloat16(v - __bfloat162float(h));
}

// ---------------- prep: fused weight [W_fx | W_x(.)W_slice]^T -> bf16 hi/lo ----
__global__ void prep_weights(const float* __restrict__ W_fx, const float* __restrict__ b_fx,
                             const float* __restrict__ W_x, const float* __restrict__ b_x,
                             const float* __restrict__ W_slice, const float* __restrict__ b_slice) {
    int k = blockIdx.x;          // 0..255
    int t = threadIdx.x;         // 0..255
    for (int c = t; c < 512; c += 256)
        split_store(W_fx[k * 512 + c], &g_bWh[(size_t)c * 256 + k], &g_bWl[(size_t)c * 256 + k]);
    {
        int h = t >> 5, s = t & 31;
        float a = 0.f;
        #pragma unroll
        for (int d = 0; d < 64; d++)
            a += W_x[k * 512 + h * 64 + d] * W_slice[d * 32 + s];
        split_store(a, &g_bWh[(size_t)(512 + t) * 256 + k], &g_bWl[(size_t)(512 + t) * 256 + k]);
    }
    if (k == 0) {
        for (int c = t; c < 512; c += 256) g_bigb[c] = b_fx[c];
        int h = t >> 5, s = t & 31;
        float bb = b_slice[s];
        #pragma unroll
        for (int d = 0; d < 64; d++)
            bb += b_x[h * 64 + d] * W_slice[d * 32 + s];
        g_bigb[512 + t] = bb;
    }
}

__global__ void zero_acc() {
    int i = blockIdx.x * blockDim.x + threadIdx.x;
    if (i < Bg * Hh * Ss * Dd) g_st[i] = 0.f;
    if (i < Bg * Hh * Ss) g_sn[i] = 0.f;
}

// ========== split-bf16 HMMA fused GEMM: g_cat = x @ bigW + bias ===============
// Block tile 128x128, K=256 in 8 chunks of 32. 8 warps = 4(m) x 2(n), warp 32x64.
__global__ __launch_bounds__(256, 2) void fused_gemm_mma(int M, const float* __restrict__ x) {
    __shared__ __align__(16) uint32_t Ahi[128 * PADK / 2];
    __shared__ __align__(16) uint32_t Alo[128 * PADK / 2];
    __shared__ __align__(16) uint32_t Bhi[128 * PADK / 2];
    __shared__ __align__(16) uint32_t Blo[128 * PADK / 2];

    int tid = threadIdx.x, wid = tid >> 5, lane = tid & 31;
    int bx = blockIdx.x, by = blockIdx.y;
    int row0 = by * 128, n0 = bx * 128;
    int warp_m = (wid & 3) * 32, warp_n = (wid >> 2) * 64;

    float acc[2][8][4];
    #pragma unroll
    for (int mi = 0; mi < 2; mi++)
        #pragma unroll
        for (int ni = 0; ni < 8; ni++)
            #pragma unroll
            for (int j = 0; j < 4; j++) acc[mi][ni][j] = 0.f;

    int a_row = ((lane >> 3) & 1) * 8 + (lane & 7);
    int a_col = (lane >> 4) * 8;
    int b_row = ((lane >> 4) & 1) * 8 + (lane & 7);
    int b_col = ((lane >> 3) & 1) * 8;

    uint32_t sAhi = smem_u32(Ahi), sAlo = smem_u32(Alo);
    uint32_t sBhi = smem_u32(Bhi), sBlo = smem_u32(Blo);

    int lrow = tid >> 1;                 // 0..127
    int lc0 = (tid & 1) * 16;            // 0 or 16

    for (int c = 0; c < 8; c++) {
        int k0 = c * 32;
        // ---- A chunk 128x32 fp32 -> bf16 hi/lo ----
        {
            int gr = row0 + lrow;
            const float* src = x + (size_t)gr * 256 + k0 + lc0;
            uint32_t* dh = &Ahi[(lrow * PADK + lc0) >> 1];
            uint32_t* dl = &Alo[(lrow * PADK + lc0) >> 1];
            #pragma unroll
            for (int i = 0; i < 4; i++) {
                float4 v = (gr < M) ? *(const float4*)(src + i * 4)
                                    : make_float4(0.f, 0.f, 0.f, 0.f);
                uint32_t h0, h1, l0, l1;
                split4(v, h0, h1, l0, l1);
                dh[i * 2] = h0; dh[i * 2 + 1] = h1;
                dl[i * 2] = l0; dl[i * 2 + 1] = l1;
            }
        }
        // ---- B chunk 128x32: direct bf16 hi/lo loads ----
        {
            const uint4* sh = (const uint4*)&g_bWh[(size_t)(n0 + lrow) * 256 + k0 + lc0];
            const uint4* sl = (const uint4*)&g_bWl[(size_t)(n0 + lrow) * 256 + k0 + lc0];
            uint32_t* dh = &Bhi[(lrow * PADK + lc0) >> 1];
            uint32_t* dl = &Blo[(lrow * PADK + lc0) >> 1];
            uint4 h0 = sh[0], h1 = sh[1], l0 = sl[0], l1 = sl[1];
            dh[0] = h0.x; dh[1] = h0.y; dh[2] = h0.z; dh[3] = h0.w;
            dh[4] = h1.x; dh[5] = h1.y; dh[6] = h1.z; dh[7] = h1.w;
            dl[0] = l0.x; dl[1] = l0.y; dl[2] = l0.z; dl[3] = l0.w;
            dl[4] = l1.x; dl[5] = l1.y; dl[6] = l1.z; dl[7] = l1.w;
        }
        __syncthreads();

        #pragma unroll
        for (int p = 0; p < 3; p++) {
            uint32_t sA = (p == 2) ? sAlo : sAhi;
            uint32_t sB = (p == 1) ? sBlo : sBhi;
            #pragma unroll
            for (int ks = 0; ks < 2; ks++) {
                int kb = ks * 16;
                uint32_t af[2][4];
                #pragma unroll
                for (int mi = 0; mi < 2; mi++)
                    ldsm_x4(af[mi], sA + ((warp_m + mi * 16 + a_row) * PADK + kb + a_col) * 2);
                uint32_t bfr[8][2];
                #pragma unroll
                for (int nj = 0; nj < 4; nj++) {
                    uint32_t r[4];
                    ldsm_x4(r, sB + ((warp_n + nj * 16 + b_row) * PADK + kb + b_col) * 2);
                    bfr[nj * 2][0] = r[0]; bfr[nj * 2][1] = r[1];
                    bfr[nj * 2 + 1][0] = r[2]; bfr[nj * 2 + 1][1] = r[3];
                }
                #pragma unroll
                for (int mi = 0; mi < 2; mi++)
                    #pragma unroll
                    for (int ni = 0; ni < 8; ni++)
                        mma_bf16(acc[mi][ni], af[mi], bfr[ni]);
            }
        }
        __syncthreads();
    }

    // ---- epilogue: add bias, store fp32 to g_cat ----
    int r_in = lane >> 2, c_in = (lane & 3) * 2;
    #pragma unroll
    for (int mi = 0; mi < 2; mi++) {
        #pragma unroll
        for (int ni = 0; ni < 8; ni++) {
            int gc = n0 + warp_n + ni * 8 + c_in;
            float b0 = g_bigb[gc], b1 = g_bigb[gc + 1];
            int gr0 = row0 + warp_m + mi * 16 + r_in;
            if (gr0 < M) {
                float2 o = make_float2(acc[mi][ni][0] + b0, acc[mi][ni][1] + b1);
                *(float2*)&g_cat[(size_t)gr0 * 768 + gc] = o;
            }
            int gr1 = gr0 + 8;
            if (gr1 < M) {
                float2 o = make_float2(acc[mi][ni][2] + b0, acc[mi][ni][3] + b1);
                *(float2*)&g_cat[(size_t)gr1 * 768 + gc] = o;
            }
        }
    }
}

// --------- tempered softmax over S=32; fp32 in place + bf16 hi/lo out ----------
__global__ void softmax_kernel(const float* __restrict__ temp, int total) {
    int gw = blockIdx.x * 8 + (threadIdx.x >> 5);
    int lane = threadIdx.x & 31;
    if (gw >= total) return;
    int n = gw >> 3, h = gw & 7;
    float* p = &g_cat[(size_t)n * 768 + 512 + h * 32 + lane];
    float v = *p / temp[h];
    float m = v;
    #pragma unroll
    for (int o = 16; o; o >>= 1) m = fmaxf(m, __shfl_xor_sync(0xffffffffu, m, o));
    float e = __expf(v - m);
    float s = e;
    #pragma unroll
    for (int o = 16; o; o >>= 1) s += __shfl_xor_sync(0xffffffffu, s, o);
    float r = e / s;
    *p = r;
    size_t idx = (size_t)n * 256 + h * 32 + lane;
    split_store(r, &g_wh[idx], &g_wl[idx]);
}

// ---------------- sync-free scatter: warp-per-h, lane-per-s -------------------
__global__ void scatter_kernel(const int* __restrict__ batch, int N) {
    int h = threadIdx.x >> 5;
    int lane = threadIdx.x & 31;
    int start = blockIdx.x * CHUNK;
    int end = min(start + CHUNK, N);

    float acc[64];
    #pragma unroll
    for (int d = 0; d < 64; d++) acc[d] = 0.f;
    float accn = 0.f;
    int cur_b = __ldg(&batch[start]);

    for (int n = start; n < end; n++) {
        int bn = __ldg(&batch[n]);
        if (bn != cur_b) {
            float* st = g_st + (((size_t)cur_b * 8 + h) * 32 + lane) * 64;
            #pragma unroll
            for (int d = 0; d < 64; d++) { atomicAdd(&st[d], acc[d]); acc[d] = 0.f; }
            atomicAdd(&g_sn[(cur_b * 8 + h) * 32 + lane], accn);
            accn = 0.f;
            cur_b = bn;
        }
        const float* row = &g_cat[(size_t)n * 768];
        float wv = row[512 + h * 32 + lane];
        float f0 = row[h * 64 + lane];
        float f1 = row[h * 64 + 32 + lane];
        accn += wv;
        #pragma unroll
        for (int d = 0; d < 32; d++) {
            acc[d]      += wv * __shfl_sync(0xffffffffu, f0, d);
            acc[d + 32] += wv * __shfl_sync(0xffffffffu, f1, d);
        }
    }
    float* st = g_st + (((size_t)cur_b * 8 + h) * 32 + lane) * 64;
    #pragma unroll
    for (int d = 0; d < 64; d++) atomicAdd(&st[d], acc[d]);
    atomicAdd(&g_sn[(cur_b * 8 + h) * 32 + lane], accn);
}

// ---------------- tiny attention over slice tokens, one block per (b,h) --------
__global__ void attention_kernel(const float* __restrict__ W_q, const float* __restrict__ W_k,
                                 const float* __restrict__ W_v) {
    int bh = blockIdx.x;
    __shared__ float st[32 * 64];
    __shared__ float q[32 * 64];
    __shared__ float kT[64 * 33];
    __shared__ float v[32 * 64];
    __shared__ float attn[32 * 32];
    int tid = threadIdx.x;
    const float* base = g_st + (size_t)bh * 2048;
    const float* nrm = g_sn + bh * 32;

    for (int i = tid; i < 2048; i += 256) {
        int s = i >> 6;
        st[i] = base[i] / (nrm[s] + 1e-5f);
    }
    __syncthreads();
    for (int i = tid; i < 2048; i += 256) {
        int s = i >> 6, e = i & 63;
        float aq = 0.f, ak = 0.f, av = 0.f;
        #pragma unroll
        for (int d = 0; d < 64; d++) {
            float sv = st[s * 64 + d];
            aq += sv * W_q[d * 64 + e];
            ak += sv * W_k[d * 64 + e];
            av += sv * W_v[d * 64 + e];
        }
        q[i] = aq; kT[e * 33 + s] = ak; v[i] = av;
    }
    __syncthreads();
    for (int i = tid; i < 1024; i += 256) {
        int s = i >> 5, t = i & 31;
        float a = 0.f;
        #pragma unroll
        for (int d = 0; d < 64; d++) a += q[s * 64 + d] * kT[d * 33 + t];
        attn[i] = a * 0.125f;
    }
    __syncthreads();
    int warp = tid >> 5, lane = tid & 31;
    for (int r = warp; r < 32; r += 8) {
        float val = attn[r * 32 + lane];
        float m = val;
        #pragma unroll
        for (int o = 16; o; o >>= 1) m = fmaxf(m, __shfl_xor_sync(0xffffffffu, m, o));
        float e = __expf(val - m);
        float ssum = e;
        #pragma unroll
        for (int o = 16; o; o >>= 1) ssum += __shfl_xor_sync(0xffffffffu, ssum, o);
        attn[r * 32 + lane] = e / ssum;
    }
    __syncthreads();
    float* ob = g_ot + (size_t)bh * 2048;
    for (int i = tid; i < 2048; i += 256) {
        int s = i >> 6, d = i & 63;
        float a = 0.f;
        #pragma unroll
        for (int t = 0; t < 32; t++) a += attn[s * 32 + t] * v[t * 64 + d];
        ob[i] = a;
    }
}

// --------- fold out_tok with W_out -> M1 TRANSPOSED bf16 hi/lo [b][j][hs] ------
__global__ void build_m1(const float* __restrict__ W_out) {
    int bh = blockIdx.x;
    int h = bh & 7, b = bh >> 3;
    __shared__ float ot[2048];
    int tid = threadIdx.x;
    for (int i = tid; i < 2048; i += 256) ot[i] = g_ot[(size_t)bh * 2048 + i];
    __syncthreads();
    for (int i = tid; i < 8192; i += 256) {
        int s = i >> 8, j = i & 255;
        float a = 0.f;
        #pragma unroll
        for (int d = 0; d < 64; d++)
            a += ot[s * 64 + d] * W_out[(h * 64 + d) * 256 + j];
        size_t idx = ((size_t)b * 256 + j) * 256 + (h * 32 + s);
        split_store(a, &g_m1h[idx], &g_m1l[idx]);
    }
}

// ===== final: out[n,:] = w[n,:] @ M1[batch[n]] + b_out (split-bf16 HMMA) ======
__global__ __launch_bounds__(256, 2) void final_gemm_mma(
    int M, const int* __restrict__ batch,
    const float* __restrict__ bias, float* __restrict__ C)
{
    __shared__ __align__(16) uint32_t Ahi[128 * PADK / 2];
    __shared__ __align__(16) uint32_t Alo[128 * PADK / 2];
    __shared__ __align__(16) uint32_t Bhi[128 * PADK / 2];
    __shared__ __align__(16) uint32_t Blo[128 * PADK / 2];
    __shared__ int sb[128];

    int tid = threadIdx.x, wid = tid >> 5, lane = tid & 31;
    int bx = blockIdx.x, by = blockIdx.y;
    int row0 = by * 128, n0 = bx * 128;
    int rows = min(128, M - row0);
    int warp_m = (wid & 3) * 32, warp_n = (wid >> 2) * 64;

    for (int i = tid; i < 128; i += 256) sb[i] = (i < rows) ? batch[row0 + i] : -1;
    __syncthreads();
    int b_first = sb[0], b_last = sb[rows - 1];

    int a_row = ((lane >> 3) & 1) * 8 + (lane & 7);
    int a_col = (lane >> 4) * 8;
    int b_row = ((lane >> 4) & 1) * 8 + (lane & 7);
    int b_col = ((lane >> 3) & 1) * 8;

    uint32_t sAhi = smem_u32(Ahi), sAlo = smem_u32(Alo);
    uint32_t sBhi = smem_u32(Bhi), sBlo = smem_u32(Blo);

    int lrow = tid >> 1;
    int lc0 = (tid & 1) * 16;
    int r_in = lane >> 2, c_in = (lane & 3) * 2;

    for (int bb = b_first; bb <= b_last; bb++) {
        float acc[2][8][4];
        #pragma unroll
        for (int mi = 0; mi < 2; mi++)
            #pragma unroll
            for (int ni = 0; ni < 8; ni++)
                #pragma unroll
                for (int j = 0; j < 4; j++) acc[mi][ni][j] = 0.f;

        const __nv_bfloat16* Bh = g_m1h + (size_t)bb * 65536;
        const __nv_bfloat16* Bl = g_m1l + (size_t)bb * 65536;

        for (int c = 0; c < 8; c++) {
            int k0 = c * 32;
            // ---- A chunk: w bf16 hi/lo [128 x 32] ----
            {
                int gr = row0 + lrow;
                uint32_t* dh = &Ahi[(lrow * PADK + lc0) >> 1];
                uint32_t* dl = &Alo[(lrow * PADK + lc0) >> 1];
                if (gr < M) {
                    const uint4* sh = (const uint4*)&g_wh[(size_t)gr * 256 + k0 + lc0];
                    const uint4* sl = (const uint4*)&g_wl[(size_t)gr * 256 + k0 + lc0];
                    uint4 h0 = sh[0], h1 = sh[1], l0 = sl[0], l1 = sl[1];
                    dh[0] = h0.x; dh[1] = h0.y; dh[2] = h0.z; dh[3] = h0.w;
                    dh[4] = h1.x; dh[5] = h1.y; dh[6] = h1.z; dh[7] = h1.w;
                    dl[0] = l0.x; dl[1] = l0.y; dl[2] = l0.z; dl[3] = l0.w;
                    dl[4] = l1.x; dl[5] = l1.y; dl[6] = l1.z; dl[7] = l1.w;
                } else {
                    #pragma unroll
                    for (int i = 0; i < 8; i++) { dh[i] = 0u; dl[i] = 0u; }
                }
            }
            // ---- B chunk: M1t bf16 hi/lo [128 x 32] ----
            {
                const uint4* sh = (const uint4*)&Bh[(size_t)(n0 + lrow) * 256 + k0 + lc0];
                const uint4* sl = (const uint4*)&Bl[(size_t)(n0 + lrow) * 256 + k0 + lc0];
                uint32_t* dh = &Bhi[(lrow * PADK + lc0) >> 1];
                uint32_t* dl = &Blo[(lrow * PADK + lc0) >> 1];
                uint4 h0 = sh[0], h1 = sh[1], l0 = sl[0], l1 = sl[1];
                dh[0] = h0.x; dh[1] = h0.y; dh[2] = h0.z; dh[3] = h0.w;
                dh[4] = h1.x; dh[5] = h1.y; dh[6] = h1.z; dh[7] = h1.w;
                dl[0] = l0.x; dl[1] = l0.y; dl[2] = l0.z; dl[3] = l0.w;
                dl[4] = l1.x; dl[5] = l1.y; dl[6] = l1.z; dl[7] = l1.w;
            }
            __syncthreads();

            #pragma unroll
            for (int p = 0; p < 3; p++) {
                uint32_t sA = (p == 2) ? sAlo : sAhi;
                uint32_t sB = (p == 1) ? sBlo : sBhi;
                #pragma unroll
                for (int ks = 0; ks < 2; ks++) {
                    int kb = ks * 16;
                    uint32_t af[2][4];
                    #pragma unroll
                    for (int mi = 0; mi < 2; mi++)
                        ldsm_x4(af[mi], sA + ((warp_m + mi * 16 + a_row) * PADK + kb + a_col) * 2);
                    uint32_t bfr[8][2];
                    #pragma unroll
                    for (int nj = 0; nj < 4; nj++) {
                        uint32_t r[4];
                        ldsm_x4(r, sB + ((warp_n + nj * 16 + b_row) * PADK + kb + b_col) * 2);
                        bfr[nj * 2][0] = r[0]; bfr[nj * 2][1] = r[1];
                        bfr[nj * 2 + 1][0] = r[2]; bfr[nj * 2 + 1][1] = r[3];
                    }
                    #pragma unroll
                    for (int mi = 0; mi < 2; mi++)
                        #pragma unroll
                        for (int ni = 0; ni < 8; ni++)
                            mma_bf16(acc[mi][ni], af[mi], bfr[ni]);
                }
            }
            __syncthreads();
        }

        // ---- epilogue: rows belonging to bb only ----
        #pragma unroll
        for (int mi = 0; mi < 2; mi++) {
            #pragma unroll
            for (int ni = 0; ni < 8; ni++) {
                int gc = n0 + warp_n + ni * 8 + c_in;
                float b0 = bias[gc], b1 = bias[gc + 1];
                int lr0 = warp_m + mi * 16 + r_in;
                int gr0 = row0 + lr0;
                if (gr0 < M && sb[lr0] == bb) {
                    float2 o = make_float2(acc[mi][ni][0] + b0, acc[mi][ni][1] + b1);
                    *(float2*)&C[(size_t)gr0 * 256 + gc] = o;
                }
                int lr1 = lr0 + 8;
                int gr1 = gr0 + 8;
                if (gr1 < M && sb[lr1] == bb) {
                    float2 o = make_float2(acc[mi][ni][2] + b0, acc[mi][ni][3] + b1);
                    *(float2*)&C[(size_t)gr1 * 256 + gc] = o;
                }
            }
        }
    }
}

// ---------------- launch ----------------
extern "C" void kernel_launch(void* const* d_in, const int* in_sizes, int n_in,
                              void* d_out, int out_size) {
    const float* x       = (const float*)d_in[0];
    const int*   batch   = (const int*)d_in[1];
    const float* W_fx    = (const float*)d_in[2];
    const float* b_fx    = (const float*)d_in[3];
    const float* W_x     = (const float*)d_in[4];
    const float* b_x     = (const float*)d_in[5];
    const float* W_slice = (const float*)d_in[6];
    const float* b_slice = (const float*)d_in[7];
    const float* gtemp   = (const float*)d_in[8];
    const float* W_q     = (const float*)d_in[9];
    const float* W_k     = (const float*)d_in[10];
    const float* W_v     = (const float*)d_in[11];
    const float* W_out   = (const float*)d_in[12];
    const float* b_out   = (const float*)d_in[13];
    float* out = (float*)d_out;

    int n = in_sizes[1];
    int rowBlocks = (n + 127) / 128;

    // 1. build fused weight bf16 hi/lo + bias
    prep_weights<<<256, 256>>>(W_fx, b_fx, W_x, b_x, W_slice, b_slice);
    // 2. zero scatter accumulators
    zero_acc<<<512, 256>>>();
    // 3. split-bf16 HMMA fused GEMM: [fx | logits] = x @ bigW + bigb
    fused_gemm_mma<<<dim3(6, rowBlocks), 256>>>(n, x);
    // 4. tempered softmax over S (fp32 in place + bf16 hi/lo)
    softmax_kernel<<<n, 256>>>(gtemp, n * 8);
    // 5. scatter-add pooling
    scatter_kernel<<<rowBlocks, 256>>>(batch, n);
    // 6. tiny attention over slice tokens
    attention_kernel<<<64, 256>>>(W_q, W_k, W_v);
    // 7. fold out_tok with W_out -> transposed bf16 hi/lo M1
    build_m1<<<64, 256>>>(W_out);
    // 8. out = w @ M1[batch] + b_out   (split-bf16 HMMA)
    final_gemm_mma<<<dim3(2, rowBlocks), 256>>>(n, batch, b_out, out);
}